// round 15
// baseline (speedup 1.0000x reference)
#include <cuda_runtime.h>
#include <math.h>
#include <stdint.h>

#define BB 2
#define NN 128
#define HH 2
#define DM 512
#define DK 256
#define BHN 512
#define SCALE 0.005524271728019903f   // 1/sqrt(128*256)
#define OUT_ELEMS (BB*NN*NN*DM)        // 16777216

#define QKV_STRIDE (BHN*DK)            // 131072
#define BX_STRIDE  (BB*NN*DK)          // 65536
#define VW_STRIDE  (BHN*2*DM)          // 524288
#define BW_STRIDE  (BB*NN*2*DM)        // 262144

// projA split-K=4 partials (contiguous: consumers sum by stride)
__device__ float g_qp[4][QKV_STRIDE];
__device__ float g_kp[4][QKV_STRIDE];
__device__ float g_vp[4][QKV_STRIDE];
__device__ float g_bxp[4][BX_STRIDE];

__device__ float g_A[BHN];
__device__ float g_Bq[BHN];
__device__ float g_Ck[BHN];
__device__ float g_Dd[BB*NN];

// projB split-K=2 partials
__device__ float g_Vw[2][VW_STRIDE];    // [(bh,j)][hp][o]
__device__ float g_Bw[2][BW_STRIDE];    // [(b,j)][hp][o]

// Phase counters (reset by last stage-2 block each run)
__device__ unsigned g_cA;      // projA completions  (224)
__device__ unsigned g_cDots;   // dots completions   (64)
__device__ unsigned g_cS2;     // stage2 completions (256)

__device__ __forceinline__ float to_tf32(float x) {
    float r; asm("cvt.rna.tf32.f32 %0, %1;" : "=f"(r) : "f"(x)); return r;
}
__device__ __forceinline__ void mma_tf32(float* c,
        uint32_t a0, uint32_t a1, uint32_t a2, uint32_t a3,
        uint32_t b0, uint32_t b1) {
    asm volatile("mma.sync.aligned.m16n8k8.row.col.f32.tf32.tf32.f32 "
        "{%0,%1,%2,%3},{%4,%5,%6,%7},{%8,%9},{%0,%1,%2,%3};"
        : "+f"(c[0]), "+f"(c[1]), "+f"(c[2]), "+f"(c[3])
        : "r"(a0), "r"(a1), "r"(a2), "r"(a3), "r"(b0), "r"(b1));
}

__device__ __forceinline__ void spin_until(volatile unsigned* cnt, unsigned target)
{
    if (threadIdx.x == 0) {
        while (atomicAdd((unsigned*)cnt, 0u) < target) __nanosleep(64);
    }
    __syncthreads();
    __threadfence();
}
__device__ __forceinline__ void arrive(unsigned* cnt)
{
    __syncthreads();
    if (threadIdx.x == 0) {
        __threadfence();
        atomicAdd(cnt, 1u);
    }
}

// Streaming (evict-first) 128-bit store
__device__ __forceinline__ void stcs4(float* p, float4 v)
{
    asm volatile("st.global.cs.v4.f32 [%0], {%1,%2,%3,%4};"
                 :: "l"(p), "f"(v.x), "f"(v.y), "f"(v.z), "f"(v.w) : "memory");
}

// ---------------------------------------------------------------------------
// tf32 64x128 block GEMM core. 256 threads = 8 warps (2x4), warp tile 32x32.
// k-tile 16, double-buffered. A operand = sum of NSUM arrays at stride pstr.
// ---------------------------------------------------------------------------
struct TCSmem {
    float sA[2][16][72];
    float sB[2][16][136];
};

template<int KC, int NSUM>
__device__ __forceinline__ void gemm_tile_tc(
        const float* __restrict__ A0, size_t pstr, int astride,
        const float* __restrict__ W, int wcols, int row0, int col0,
        TCSmem& s, float cacc[2][4][4])
{
    const int t = threadIdx.x;
    const int lane = t & 31, warp = t >> 5;
    const int wm = (warp & 1) * 32, wn = (warp >> 1) * 32;
    const int gid = lane >> 2, tig = lane & 3;
    const int a_r = t >> 2;
    const int a_q = (t & 3) * 4;
    const int b_k = t >> 5;
    const int b_c = (t & 31) * 4;
    constexpr int NK = KC / 16;

    auto loadA = [&](int k0) -> float4 {
        size_t off = (size_t)(row0 + a_r) * astride + k0 + a_q;
        float4 r = *(const float4*)&A0[off];
#pragma unroll
        for (int i = 1; i < NSUM; ++i) {
            float4 x = *(const float4*)&A0[i * pstr + off];
            r.x += x.x; r.y += x.y; r.z += x.z; r.w += x.w;
        }
        return r;
    };

    float4 ra, rb[2];
    ra = loadA(0);
#pragma unroll
    for (int l = 0; l < 2; ++l)
        rb[l] = *(const float4*)&W[(size_t)(b_k + 8 * l) * wcols + col0 + b_c];
    {
        s.sA[0][a_q + 0][a_r] = to_tf32(ra.x);
        s.sA[0][a_q + 1][a_r] = to_tf32(ra.y);
        s.sA[0][a_q + 2][a_r] = to_tf32(ra.z);
        s.sA[0][a_q + 3][a_r] = to_tf32(ra.w);
#pragma unroll
        for (int l = 0; l < 2; ++l) {
            float4 tb;
            tb.x = to_tf32(rb[l].x); tb.y = to_tf32(rb[l].y);
            tb.z = to_tf32(rb[l].z); tb.w = to_tf32(rb[l].w);
            *(float4*)&s.sB[0][b_k + 8 * l][b_c] = tb;
        }
    }
    __syncthreads();

#pragma unroll
    for (int kt = 0; kt < NK; ++kt) {
        const int cur = kt & 1, nxt = cur ^ 1;
        if (kt + 1 < NK) {
            int k0 = (kt + 1) * 16;
            ra = loadA(k0);
#pragma unroll
            for (int l = 0; l < 2; ++l)
                rb[l] = *(const float4*)&W[(size_t)(k0 + b_k + 8 * l) * wcols + col0 + b_c];
        }
#pragma unroll
        for (int kf = 0; kf < 16; kf += 8) {
            uint32_t af[2][4], bf[4][2];
#pragma unroll
            for (int mi = 0; mi < 2; ++mi) {
                int m0 = wm + mi * 16 + gid;
                af[mi][0] = __float_as_uint(s.sA[cur][kf + tig][m0]);
                af[mi][1] = __float_as_uint(s.sA[cur][kf + tig][m0 + 8]);
                af[mi][2] = __float_as_uint(s.sA[cur][kf + tig + 4][m0]);
                af[mi][3] = __float_as_uint(s.sA[cur][kf + tig + 4][m0 + 8]);
            }
#pragma unroll
            for (int ni = 0; ni < 4; ++ni) {
                int n0 = wn + ni * 8 + gid;
                bf[ni][0] = __float_as_uint(s.sB[cur][kf + tig][n0]);
                bf[ni][1] = __float_as_uint(s.sB[cur][kf + tig + 4][n0]);
            }
#pragma unroll
            for (int mi = 0; mi < 2; ++mi)
#pragma unroll
                for (int ni = 0; ni < 4; ++ni)
                    mma_tf32(cacc[mi][ni], af[mi][0], af[mi][1], af[mi][2], af[mi][3],
                             bf[ni][0], bf[ni][1]);
        }
        if (kt + 1 < NK) {
            s.sA[nxt][a_q + 0][a_r] = to_tf32(ra.x);
            s.sA[nxt][a_q + 1][a_r] = to_tf32(ra.y);
            s.sA[nxt][a_q + 2][a_r] = to_tf32(ra.z);
            s.sA[nxt][a_q + 3][a_r] = to_tf32(ra.w);
#pragma unroll
            for (int l = 0; l < 2; ++l) {
                float4 tb;
                tb.x = to_tf32(rb[l].x); tb.y = to_tf32(rb[l].y);
                tb.z = to_tf32(rb[l].z); tb.w = to_tf32(rb[l].w);
                *(float4*)&s.sB[nxt][b_k + 8 * l][b_c] = tb;
            }
        }
        __syncthreads();
    }
}

__device__ __forceinline__ float4 sum4(const float* base, size_t str, size_t off)
{
    float4 r = *(const float4*)&base[off];
#pragma unroll
    for (int i = 1; i < 4; ++i) {
        float4 x = *(const float4*)&base[i * str + off];
        r.x += x.x; r.y += x.y; r.z += x.z; r.w += x.w;
    }
    return r;
}
__device__ __forceinline__ float4 sum2(const float* base, size_t str, size_t off)
{
    float4 r = *(const float4*)&base[off];
    float4 x = *(const float4*)&base[str + off];
    r.x += x.x; r.y += x.y; r.z += x.z; r.w += x.w;
    return r;
}

// ---------------------------------------------------------------------------
// Fused stage1+2 kernel: 480 blocks.
//   bids [0,224)   : projA (split-K 4)
//   bids [224,480) : 64 attn (dots->barrier->softmax) + 192 projB GEMM
// ---------------------------------------------------------------------------
__global__ __launch_bounds__(256) void stage12_kernel(
    const float* __restrict__ query, const float* __restrict__ key,
    const float* __restrict__ value, const float* __restrict__ boxes,
    const float* __restrict__ Wq, const float* __restrict__ bq,
    const float* __restrict__ Wk, const float* __restrict__ bk,
    const float* __restrict__ Wv, const float* __restrict__ bv,
    const float* __restrict__ Wbox, const float* __restrict__ bbox,
    const float* __restrict__ Wo, float* __restrict__ attn_out)
{
    __shared__ TCSmem s;
    const int P = blockIdx.x;
    const int t = threadIdx.x;
    const int warp = t >> 5, lane = t & 31;

    if (P < 224) {
        // ===== projA =====
        int z = P / 56;
        int rest = P - z * 56;
        int ct = rest % 14;
        int row0 = (rest / 14) * 64;
        int which = (ct < 12) ? (ct >> 2) : 3;
        int col0 = (which < 3) ? (ct & 3) * 128 : (ct - 12) * 128;

        const float* A; const float* W; const float* bias; float* outp; int wcols;
        if      (which == 0) { A = query; W = Wq;   bias = bq;   outp = g_qp[z];  wcols = DM; }
        else if (which == 1) { A = key;   W = Wk;   bias = bk;   outp = g_kp[z];  wcols = DM; }
        else if (which == 2) { A = value; W = Wv;   bias = bv;   outp = g_vp[z];  wcols = DM; }
        else                 { A = boxes; W = Wbox; bias = bbox; outp = g_bxp[z]; wcols = DK; }

        float cacc[2][4][4];
#pragma unroll
        for (int mi = 0; mi < 2; ++mi)
#pragma unroll
            for (int ni = 0; ni < 4; ++ni)
#pragma unroll
                for (int r = 0; r < 4; ++r) cacc[mi][ni][r] = 0.f;

        gemm_tile_tc<128, 1>(A + z * 128, 0, DM,
                             W + (size_t)z * 128 * wcols, wcols, row0, col0, s, cacc);

        const int wm = (warp & 1) * 32, wn = (warp >> 1) * 32;
        const int gid = lane >> 2, tig = lane & 3;
#pragma unroll
        for (int mi = 0; mi < 2; ++mi)
#pragma unroll
            for (int rr = 0; rr < 2; ++rr) {
                int row = row0 + wm + mi * 16 + rr * 8 + gid;
                int b = row >> 7, n = row & 127;
#pragma unroll
                for (int ni = 0; ni < 4; ++ni) {
                    int col = col0 + wn + ni * 8 + tig * 2;
                    float2 v;
                    float b0 = z ? 0.f : bias[col];
                    float b1 = z ? 0.f : bias[col + 1];
                    v.x = cacc[mi][ni][rr * 2 + 0] + b0;
                    v.y = cacc[mi][ni][rr * 2 + 1] + b1;
                    if (which < 3) {
                        int h = col >> 8, dk = col & 255;
                        *(float2*)&outp[(((b * HH + h) * NN) + n) * DK + dk] = v;
                    } else {
                        *(float2*)&outp[row * DK + col] = v;
                    }
                }
            }
        arrive(&g_cA);
        return;
    }

    // ===== stage 2 =====
    int p = P - 224;
    spin_until(&g_cA, 224u);

    if (p < 64) {
        // ---- dots: warp per (bh,j), sum 4 projA partials ----
        int bid = p * 8 + warp;
        int j = bid & 127;
        int bh_d = bid >> 7;
        int b_d = bh_d >> 1;

        float pa = 0.f, pb = 0.f, pc = 0.f, pd = 0.f;
#pragma unroll
        for (int u = 0; u < 2; ++u) {
            size_t off = (size_t)bid * DK + (lane + u * 32) * 4;
            size_t boff = (size_t)(b_d * NN + j) * DK + (lane + u * 32) * 4;
            float4 qv = sum4(&g_qp[0][0], QKV_STRIDE, off);
            float4 kv = sum4(&g_kp[0][0], QKV_STRIDE, off);
            float4 bv = sum4(&g_bxp[0][0], BX_STRIDE, boff);
            pa += qv.x*kv.x + qv.y*kv.y + qv.z*kv.z + qv.w*kv.w;
            pb += bv.x*kv.x + bv.y*kv.y + bv.z*kv.z + bv.w*kv.w;
            pc += qv.x*bv.x + qv.y*bv.y + qv.z*bv.z + qv.w*bv.w;
            pd += bv.x*bv.x + bv.y*bv.y + bv.z*bv.z + bv.w*bv.w;
        }
#pragma unroll
        for (int off = 16; off > 0; off >>= 1) {
            pa += __shfl_down_sync(0xffffffff, pa, off);
            pb += __shfl_down_sync(0xffffffff, pb, off);
            pc += __shfl_down_sync(0xffffffff, pc, off);
            pd += __shfl_down_sync(0xffffffff, pd, off);
        }
        if (lane == 0) {
            g_A[bid] = pa;
            g_Bq[bid] = pb;
            g_Ck[bid] = pc;
            if ((bh_d & 1) == 0) g_Dd[b_d * NN + j] = pd;
        }
        arrive(&g_cDots);
        spin_until(&g_cDots, 64u);

        // ---- softmax: warp per row, 8 rows per block ----
        int bh = p >> 4;
        int b = bh >> 1;
        __shared__ float sA[128], sCk[128];
        if (t < 128) sA[t] = g_A[bh * NN + t];
        else         sCk[t - 128] = g_Ck[bh * NN + (t - 128)];
        __syncthreads();

        float v = sA[lane] + sA[lane + 32] + sA[lane + 64] + sA[lane + 96];
#pragma unroll
        for (int off = 16; off > 0; off >>= 1)
            v += __shfl_down_sync(0xffffffff, v, off);
        float S0 = __shfl_sync(0xffffffff, v, 0);

        int n = (p & 15) * 8 + warp;
        float An = sA[n];
        float Bqn = g_Bq[bh * NN + n];
        float Ddn = g_Dd[b * NN + n];

        float sv[4], mx = -1e30f;
#pragma unroll
        for (int u = 0; u < 4; ++u) {
            int m = lane + u * 32;
            float x = (m == n) ? (S0 - An + Ddn)
                               : (S0 - An - sA[m] + Bqn + sCk[m]);
            sv[u] = x * SCALE;
            mx = fmaxf(mx, sv[u]);
        }
#pragma unroll
        for (int off = 16; off > 0; off >>= 1)
            mx = fmaxf(mx, __shfl_xor_sync(0xffffffff, mx, off));
        float e[4], tot = 0.f;
#pragma unroll
        for (int u = 0; u < 4; ++u) { e[u] = expf(sv[u] - mx); tot += e[u]; }
#pragma unroll
        for (int off = 16; off > 0; off >>= 1)
            tot += __shfl_xor_sync(0xffffffff, tot, off);
        float inv = 1.f / tot;
        size_t base = ((size_t)(bh * NN) + n) * NN;
#pragma unroll
        for (int u = 0; u < 4; ++u)
            attn_out[base + lane + u * 32] = e[u] * inv;
    } else {
        // ---- projB GEMM: split-K 2, 64x128 tiles, A = sum of 4 partials ----
        int idx = p - 64;              // 0..191
        int y = idx >> 4;              // 0..11
        int rem = idx & 15;
        int colt = rem >> 1;           // 0..7
        int ks = rem & 1;
        int col0 = colt * 128;
        int hp = col0 >> 9;
        int wcol0 = col0 & 511;

        const float* A0; size_t pstr; float* outp; int row0;
        if (y < 8) { A0 = &g_vp[0][0];  pstr = QKV_STRIDE; outp = g_Vw[ks]; row0 = y * 64; }
        else       { A0 = &g_bxp[0][0]; pstr = BX_STRIDE;  outp = g_Bw[ks]; row0 = (y - 8) * 64; }
        const float* W = Wo + (size_t)hp * DK * DM + (size_t)ks * 128 * DM;

        float cacc[2][4][4];
#pragma unroll
        for (int mi = 0; mi < 2; ++mi)
#pragma unroll
            for (int ni = 0; ni < 4; ++ni)
#pragma unroll
                for (int r = 0; r < 4; ++r) cacc[mi][ni][r] = 0.f;

        gemm_tile_tc<128, 4>(A0 + ks * 128, pstr, DK, W, DM, row0, wcol0, s, cacc);

        const int wm = (warp & 1) * 32, wn = (warp >> 1) * 32;
        const int gid = lane >> 2, tig = lane & 3;
#pragma unroll
        for (int mi = 0; mi < 2; ++mi)
#pragma unroll
            for (int rr = 0; rr < 2; ++rr) {
                int row = row0 + wm + mi * 16 + rr * 8 + gid;
#pragma unroll
                for (int ni = 0; ni < 4; ++ni) {
                    int col = wcol0 + wn + ni * 8 + tig * 2;
                    float2 v;
                    v.x = cacc[mi][ni][rr * 2 + 0];
                    v.y = cacc[mi][ni][rr * 2 + 1];
                    *(float2*)&outp[(size_t)row * (2 * DM) + hp * DM + col] = v;
                }
            }
    }

    // stage2 completion + counter reset for next replay
    __syncthreads();
    if (t == 0) {
        __threadfence();
        unsigned done = atomicAdd(&g_cS2, 1u);
        if (done == 255u) {
            g_cA = 0u; g_cDots = 0u; g_cS2 = 0u;
            __threadfence();
        }
    }
}

// ---------------------------------------------------------------------------
// Assembly: sync-free, zero smem, pipelined shfl broadcast, streaming stores.
// __launch_bounds__(256, 6) caps regs to raise occupancy.
// Block per (b, jp, iq): 1024 x 256. out[b,i,jp,:] = base + a0*d0 + a1*d1
// ---------------------------------------------------------------------------
__global__ __launch_bounds__(256, 6) void assemble_kernel(
    const float* __restrict__ bo, const float* __restrict__ attn,
    float* __restrict__ out)
{
    int bid = blockIdx.x;
    int iq = bid & 3;
    int bjp = bid >> 2;
    int jp = bjp & 127, b = bjp >> 7;
    int h = jp >> 6, jj = jp & 63;
    int j0 = 2 * jj, j1 = j0 + 1;
    int bh = b * HH + h;

    int t = threadIdx.x;
    int lane = t & 31;
    int sub = t >> 7;
    int c4 = (t & 127) * 4;

    int itn = lane & 15;
    int i_pre = iq * 32 + itn * 2 + sub;
    float aval = attn[((size_t)(bh * NN) + i_pre) * NN + j0 + (lane >> 4)];

    float4 v0 = sum2(&g_Vw[0][0], VW_STRIDE, (size_t)((bh * NN + j0) * 2 + 0) * DM + c4);
    float4 v1 = sum2(&g_Vw[0][0], VW_STRIDE, (size_t)((bh * NN + j1) * 2 + 1) * DM + c4);
    float4 w0 = sum2(&g_Bw[0][0], BW_STRIDE, (size_t)((b  * NN + j0) * 2 + 0) * DM + c4);
    float4 w1 = sum2(&g_Bw[0][0], BW_STRIDE, (size_t)((b  * NN + j1) * 2 + 1) * DM + c4);
    float4 bb = *(const float4*)&bo[c4];

    float4 rb, r0, r1;
    rb.x = v0.x + v1.x + bb.x; rb.y = v0.y + v1.y + bb.y;
    rb.z = v0.z + v1.z + bb.z; rb.w = v0.w + v1.w + bb.w;
    r0.x = w0.x - v0.x; r0.y = w0.y - v0.y; r0.z = w0.z - v0.z; r0.w = w0.w - v0.w;
    r1.x = w1.x - v1.x; r1.y = w1.y - v1.y; r1.z = w1.z - v1.z; r1.w = w1.w - v1.w;

    float a0c = __shfl_sync(0xffffffff, aval, 0);
    float a1c = __shfl_sync(0xffffffff, aval, 16);
#pragma unroll
    for (int it = 0; it < 16; ++it) {
        float a0 = a0c, a1 = a1c;
        if (it < 15) {
            a0c = __shfl_sync(0xffffffff, aval, it + 1);
            a1c = __shfl_sync(0xffffffff, aval, it + 17);
        }
        int i = iq * 32 + it * 2 + sub;
        float4 r;
        r.x = rb.x + a0 * r0.x + a1 * r1.x;
        r.y = rb.y + a0 * r0.y + a1 * r1.y;
        r.z = rb.z + a0 * r0.z + a1 * r1.z;
        r.w = rb.w + a0 * r0.w + a1 * r1.w;
        stcs4(&out[(((size_t)(b * NN + i) * NN) + jp) * DM + c4], r);
    }
}

// ---------------------------------------------------------------------------
extern "C" void kernel_launch(void* const* d_in, const int* in_sizes, int n_in,
                              void* d_out, int out_size)
{
    const float* query = (const float*)d_in[0];
    const float* key   = (const float*)d_in[1];
    const float* value = (const float*)d_in[2];
    const float* boxes = (const float*)d_in[3];
    const float* Wq = (const float*)d_in[4];
    const float* bq = (const float*)d_in[5];
    const float* Wk = (const float*)d_in[6];
    const float* bk = (const float*)d_in[7];
    const float* Wv = (const float*)d_in[8];
    const float* bv = (const float*)d_in[9];
    const float* Wbox = (const float*)d_in[10];
    const float* bbox = (const float*)d_in[11];
    const float* Wo = (const float*)d_in[12];
    const float* bo = (const float*)d_in[13];

    float* out = (float*)d_out;
    float* attn_out = out + OUT_ELEMS;

    stage12_kernel<<<480, 256>>>(query, key, value, boxes,
                                 Wq, bq, Wk, bk, Wv, bv, Wbox, bbox,
                                 Wo, attn_out);
    assemble_kernel<<<BB * NN * 4, 256>>>(bo, attn_out, out);
}

// round 16
// speedup vs baseline: 1.0199x; 1.0199x over previous
#include <cuda_runtime.h>
#include <math.h>
#include <stdint.h>

#define BB 2
#define NN 128
#define HH 2
#define DM 512
#define DK 256
#define BHN 512
#define SCALE 0.005524271728019903f   // 1/sqrt(128*256)
#define OUT_ELEMS (BB*NN*NN*DM)        // 16777216

#define QKV_STRIDE (BHN*DK)            // 131072
#define BX_STRIDE  (BB*NN*DK)          // 65536
#define VW_STRIDE  (BHN*2*DM)          // 524288
#define BW_STRIDE  (BB*NN*2*DM)        // 262144

// projA split-K=4 partials (contiguous: consumers sum by stride)
__device__ float g_qp[4][QKV_STRIDE];
__device__ float g_kp[4][QKV_STRIDE];
__device__ float g_vp[4][QKV_STRIDE];
__device__ float g_bxp[4][BX_STRIDE];

__device__ float g_A[BHN];
__device__ float g_Bq[BHN];
__device__ float g_Ck[BHN];
__device__ float g_Dd[BB*NN];

// projB split-K=2 partials
__device__ float g_Vw[2][VW_STRIDE];    // [(bh,j)][hp][o]
__device__ float g_Bw[2][BW_STRIDE];    // [(b,j)][hp][o]

// Phase counters (reset by the 256th stage2 completion each run)
__device__ unsigned g_cVB;     // projA v/bx tile completions (96)
__device__ unsigned g_cQK;     // projA q/k tile completions  (128)
__device__ unsigned g_cDots;   // dots completions            (64)
__device__ unsigned g_cS2;     // stage2 completions          (256)

__device__ __forceinline__ float to_tf32(float x) {
    float r; asm("cvt.rna.tf32.f32 %0, %1;" : "=f"(r) : "f"(x)); return r;
}
__device__ __forceinline__ void mma_tf32(float* c,
        uint32_t a0, uint32_t a1, uint32_t a2, uint32_t a3,
        uint32_t b0, uint32_t b1) {
    asm volatile("mma.sync.aligned.m16n8k8.row.col.f32.tf32.tf32.f32 "
        "{%0,%1,%2,%3},{%4,%5,%6,%7},{%8,%9},{%0,%1,%2,%3};"
        : "+f"(c[0]), "+f"(c[1]), "+f"(c[2]), "+f"(c[3])
        : "r"(a0), "r"(a1), "r"(a2), "r"(a3), "r"(b0), "r"(b1));
}

__device__ __forceinline__ void spin_until(volatile unsigned* cnt, unsigned target)
{
    if (threadIdx.x == 0) {
        while (atomicAdd((unsigned*)cnt, 0u) < target) __nanosleep(64);
    }
    __syncthreads();
    __threadfence();
}
__device__ __forceinline__ void arrive(unsigned* cnt)
{
    __syncthreads();
    if (threadIdx.x == 0) {
        __threadfence();
        atomicAdd(cnt, 1u);
    }
}

// Streaming (evict-first) 128-bit store
__device__ __forceinline__ void stcs4(float* p, float4 v)
{
    asm volatile("st.global.cs.v4.f32 [%0], {%1,%2,%3,%4};"
                 :: "l"(p), "f"(v.x), "f"(v.y), "f"(v.z), "f"(v.w) : "memory");
}

// ---------------------------------------------------------------------------
// tf32 64x128 block GEMM core. 256 threads = 8 warps (2x4), warp tile 32x32.
// k-tile 16, double-buffered. A operand = sum of NSUM arrays at stride pstr.
// ---------------------------------------------------------------------------
struct TCSmem {
    float sA[2][16][72];
    float sB[2][16][136];
};

template<int KC, int NSUM>
__device__ __forceinline__ void gemm_tile_tc(
        const float* __restrict__ A0, size_t pstr, int astride,
        const float* __restrict__ W, int wcols, int row0, int col0,
        TCSmem& s, float cacc[2][4][4])
{
    const int t = threadIdx.x;
    const int lane = t & 31, warp = t >> 5;
    const int wm = (warp & 1) * 32, wn = (warp >> 1) * 32;
    const int gid = lane >> 2, tig = lane & 3;
    const int a_r = t >> 2;
    const int a_q = (t & 3) * 4;
    const int b_k = t >> 5;
    const int b_c = (t & 31) * 4;
    constexpr int NK = KC / 16;

    auto loadA = [&](int k0) -> float4 {
        size_t off = (size_t)(row0 + a_r) * astride + k0 + a_q;
        float4 r = *(const float4*)&A0[off];
#pragma unroll
        for (int i = 1; i < NSUM; ++i) {
            float4 x = *(const float4*)&A0[i * pstr + off];
            r.x += x.x; r.y += x.y; r.z += x.z; r.w += x.w;
        }
        return r;
    };

    float4 ra, rb[2];
    ra = loadA(0);
#pragma unroll
    for (int l = 0; l < 2; ++l)
        rb[l] = *(const float4*)&W[(size_t)(b_k + 8 * l) * wcols + col0 + b_c];
    {
        s.sA[0][a_q + 0][a_r] = to_tf32(ra.x);
        s.sA[0][a_q + 1][a_r] = to_tf32(ra.y);
        s.sA[0][a_q + 2][a_r] = to_tf32(ra.z);
        s.sA[0][a_q + 3][a_r] = to_tf32(ra.w);
#pragma unroll
        for (int l = 0; l < 2; ++l) {
            float4 tb;
            tb.x = to_tf32(rb[l].x); tb.y = to_tf32(rb[l].y);
            tb.z = to_tf32(rb[l].z); tb.w = to_tf32(rb[l].w);
            *(float4*)&s.sB[0][b_k + 8 * l][b_c] = tb;
        }
    }
    __syncthreads();

#pragma unroll
    for (int kt = 0; kt < NK; ++kt) {
        const int cur = kt & 1, nxt = cur ^ 1;
        if (kt + 1 < NK) {
            int k0 = (kt + 1) * 16;
            ra = loadA(k0);
#pragma unroll
            for (int l = 0; l < 2; ++l)
                rb[l] = *(const float4*)&W[(size_t)(k0 + b_k + 8 * l) * wcols + col0 + b_c];
        }
#pragma unroll
        for (int kf = 0; kf < 16; kf += 8) {
            uint32_t af[2][4], bf[4][2];
#pragma unroll
            for (int mi = 0; mi < 2; ++mi) {
                int m0 = wm + mi * 16 + gid;
                af[mi][0] = __float_as_uint(s.sA[cur][kf + tig][m0]);
                af[mi][1] = __float_as_uint(s.sA[cur][kf + tig][m0 + 8]);
                af[mi][2] = __float_as_uint(s.sA[cur][kf + tig + 4][m0]);
                af[mi][3] = __float_as_uint(s.sA[cur][kf + tig + 4][m0 + 8]);
            }
#pragma unroll
            for (int ni = 0; ni < 4; ++ni) {
                int n0 = wn + ni * 8 + gid;
                bf[ni][0] = __float_as_uint(s.sB[cur][kf + tig][n0]);
                bf[ni][1] = __float_as_uint(s.sB[cur][kf + tig + 4][n0]);
            }
#pragma unroll
            for (int mi = 0; mi < 2; ++mi)
#pragma unroll
                for (int ni = 0; ni < 4; ++ni)
                    mma_tf32(cacc[mi][ni], af[mi][0], af[mi][1], af[mi][2], af[mi][3],
                             bf[ni][0], bf[ni][1]);
        }
        if (kt + 1 < NK) {
            s.sA[nxt][a_q + 0][a_r] = to_tf32(ra.x);
            s.sA[nxt][a_q + 1][a_r] = to_tf32(ra.y);
            s.sA[nxt][a_q + 2][a_r] = to_tf32(ra.z);
            s.sA[nxt][a_q + 3][a_r] = to_tf32(ra.w);
#pragma unroll
            for (int l = 0; l < 2; ++l) {
                float4 tb;
                tb.x = to_tf32(rb[l].x); tb.y = to_tf32(rb[l].y);
                tb.z = to_tf32(rb[l].z); tb.w = to_tf32(rb[l].w);
                *(float4*)&s.sB[nxt][b_k + 8 * l][b_c] = tb;
            }
        }
        __syncthreads();
    }
}

__device__ __forceinline__ float4 sum4(const float* base, size_t str, size_t off)
{
    float4 r = *(const float4*)&base[off];
#pragma unroll
    for (int i = 1; i < 4; ++i) {
        float4 x = *(const float4*)&base[i * str + off];
        r.x += x.x; r.y += x.y; r.z += x.z; r.w += x.w;
    }
    return r;
}
__device__ __forceinline__ float4 sum2(const float* base, size_t str, size_t off)
{
    float4 r = *(const float4*)&base[off];
    float4 x = *(const float4*)&base[str + off];
    r.x += x.x; r.y += x.y; r.z += x.z; r.w += x.w;
    return r;
}

// ---------------------------------------------------------------------------
// Fused stage1+2 kernel: 480 blocks, dataflow-ordered.
//   bids [0,96)    : projA v/bx tiles (projB's only inputs)  -> g_cVB
//   bids [96,224)  : projA q/k tiles                          -> g_cQK
//   bids [224,416) : projB GEMM (spin g_cVB==96)
//   bids [416,480) : attn = dots (spin g_cVB, g_cQK) -> barrier -> softmax
// All waits point to strictly lower bids; producers fit in wave-1 residency.
// ---------------------------------------------------------------------------
__global__ __launch_bounds__(256) void stage12_kernel(
    const float* __restrict__ query, const float* __restrict__ key,
    const float* __restrict__ value, const float* __restrict__ boxes,
    const float* __restrict__ Wq, const float* __restrict__ bq,
    const float* __restrict__ Wk, const float* __restrict__ bk,
    const float* __restrict__ Wv, const float* __restrict__ bv,
    const float* __restrict__ Wbox, const float* __restrict__ bbox,
    const float* __restrict__ Wo, float* __restrict__ attn_out)
{
    __shared__ TCSmem s;
    const int P = blockIdx.x;
    const int t = threadIdx.x;
    const int warp = t >> 5, lane = t & 31;

    if (P < 224) {
        // ===== projA =====
        int which, col0, row0, z;
        if (P < 96) {
            // v/bx group first
            z = P / 24;
            int rest = P - z * 24;
            int ctl = rest % 6;
            row0 = (rest / 6) * 64;
            if (ctl < 4) { which = 2; col0 = ctl * 128; }
            else         { which = 3; col0 = (ctl - 4) * 128; }
        } else {
            int idx = P - 96;
            z = idx / 32;
            int rest = idx - z * 32;
            int ct = rest % 8;
            row0 = (rest / 8) * 64;
            which = (ct < 4) ? 0 : 1;
            col0 = (ct & 3) * 128;
        }

        const float* A; const float* W; const float* bias; float* outp; int wcols;
        if      (which == 0) { A = query; W = Wq;   bias = bq;   outp = g_qp[z];  wcols = DM; }
        else if (which == 1) { A = key;   W = Wk;   bias = bk;   outp = g_kp[z];  wcols = DM; }
        else if (which == 2) { A = value; W = Wv;   bias = bv;   outp = g_vp[z];  wcols = DM; }
        else                 { A = boxes; W = Wbox; bias = bbox; outp = g_bxp[z]; wcols = DK; }

        float cacc[2][4][4];
#pragma unroll
        for (int mi = 0; mi < 2; ++mi)
#pragma unroll
            for (int ni = 0; ni < 4; ++ni)
#pragma unroll
                for (int r = 0; r < 4; ++r) cacc[mi][ni][r] = 0.f;

        gemm_tile_tc<128, 1>(A + z * 128, 0, DM,
                             W + (size_t)z * 128 * wcols, wcols, row0, col0, s, cacc);

        const int wm = (warp & 1) * 32, wn = (warp >> 1) * 32;
        const int gid = lane >> 2, tig = lane & 3;
#pragma unroll
        for (int mi = 0; mi < 2; ++mi)
#pragma unroll
            for (int rr = 0; rr < 2; ++rr) {
                int row = row0 + wm + mi * 16 + rr * 8 + gid;
                int b = row >> 7, n = row & 127;
#pragma unroll
                for (int ni = 0; ni < 4; ++ni) {
                    int col = col0 + wn + ni * 8 + tig * 2;
                    float2 v;
                    float b0 = z ? 0.f : bias[col];
                    float b1 = z ? 0.f : bias[col + 1];
                    v.x = cacc[mi][ni][rr * 2 + 0] + b0;
                    v.y = cacc[mi][ni][rr * 2 + 1] + b1;
                    if (which < 3) {
                        int h = col >> 8, dk = col & 255;
                        *(float2*)&outp[(((b * HH + h) * NN) + n) * DK + dk] = v;
                    } else {
                        *(float2*)&outp[row * DK + col] = v;
                    }
                }
            }
        arrive((P < 96) ? &g_cVB : &g_cQK);
        return;
    }

    if (P < 416) {
        // ===== projB GEMM: needs only v/bx partials =====
        spin_until(&g_cVB, 96u);

        int idx = P - 224;             // 0..191
        int y = idx >> 4;              // 0..11
        int rem = idx & 15;
        int colt = rem >> 1;           // 0..7
        int ks = rem & 1;
        int col0 = colt * 128;
        int hp = col0 >> 9;
        int wcol0 = col0 & 511;

        const float* A0; size_t pstr; float* outp; int row0;
        if (y < 8) { A0 = &g_vp[0][0];  pstr = QKV_STRIDE; outp = g_Vw[ks]; row0 = y * 64; }
        else       { A0 = &g_bxp[0][0]; pstr = BX_STRIDE;  outp = g_Bw[ks]; row0 = (y - 8) * 64; }
        const float* W = Wo + (size_t)hp * DK * DM + (size_t)ks * 128 * DM;

        float cacc[2][4][4];
#pragma unroll
        for (int mi = 0; mi < 2; ++mi)
#pragma unroll
            for (int ni = 0; ni < 4; ++ni)
#pragma unroll
                for (int r = 0; r < 4; ++r) cacc[mi][ni][r] = 0.f;

        gemm_tile_tc<128, 4>(A0 + ks * 128, pstr, DK, W, DM, row0, wcol0, s, cacc);

        const int wm = (warp & 1) * 32, wn = (warp >> 1) * 32;
        const int gid = lane >> 2, tig = lane & 3;
#pragma unroll
        for (int mi = 0; mi < 2; ++mi)
#pragma unroll
            for (int rr = 0; rr < 2; ++rr) {
                int row = row0 + wm + mi * 16 + rr * 8 + gid;
#pragma unroll
                for (int ni = 0; ni < 4; ++ni) {
                    int col = wcol0 + wn + ni * 8 + tig * 2;
                    float2 v;
                    v.x = cacc[mi][ni][rr * 2 + 0];
                    v.y = cacc[mi][ni][rr * 2 + 1];
                    *(float2*)&outp[(size_t)row * (2 * DM) + hp * DM + col] = v;
                }
            }
    } else {
        // ===== attn: dots -> barrier -> softmax (tail blocks) =====
        int p = P - 416;               // 0..63
        spin_until(&g_cVB, 96u);
        spin_until(&g_cQK, 128u);

        // ---- dots: warp per (bh,j), sum 4 projA partials ----
        int bid = p * 8 + warp;
        int j = bid & 127;
        int bh_d = bid >> 7;
        int b_d = bh_d >> 1;

        float pa = 0.f, pb = 0.f, pc = 0.f, pd = 0.f;
#pragma unroll
        for (int u = 0; u < 2; ++u) {
            size_t off = (size_t)bid * DK + (lane + u * 32) * 4;
            size_t boff = (size_t)(b_d * NN + j) * DK + (lane + u * 32) * 4;
            float4 qv = sum4(&g_qp[0][0], QKV_STRIDE, off);
            float4 kv = sum4(&g_kp[0][0], QKV_STRIDE, off);
            float4 bv = sum4(&g_bxp[0][0], BX_STRIDE, boff);
            pa += qv.x*kv.x + qv.y*kv.y + qv.z*kv.z + qv.w*kv.w;
            pb += bv.x*kv.x + bv.y*kv.y + bv.z*kv.z + bv.w*kv.w;
            pc += qv.x*bv.x + qv.y*bv.y + qv.z*bv.z + qv.w*bv.w;
            pd += bv.x*bv.x + bv.y*bv.y + bv.z*bv.z + bv.w*bv.w;
        }
#pragma unroll
        for (int off = 16; off > 0; off >>= 1) {
            pa += __shfl_down_sync(0xffffffff, pa, off);
            pb += __shfl_down_sync(0xffffffff, pb, off);
            pc += __shfl_down_sync(0xffffffff, pc, off);
            pd += __shfl_down_sync(0xffffffff, pd, off);
        }
        if (lane == 0) {
            g_A[bid] = pa;
            g_Bq[bid] = pb;
            g_Ck[bid] = pc;
            if ((bh_d & 1) == 0) g_Dd[b_d * NN + j] = pd;
        }
        arrive(&g_cDots);
        spin_until(&g_cDots, 64u);

        // ---- softmax: warp per row, 8 rows per block ----
        int bh = p >> 4;
        int b = bh >> 1;
        __shared__ float sA[128], sCk[128];
        if (t < 128) sA[t] = g_A[bh * NN + t];
        else         sCk[t - 128] = g_Ck[bh * NN + (t - 128)];
        __syncthreads();

        float v = sA[lane] + sA[lane + 32] + sA[lane + 64] + sA[lane + 96];
#pragma unroll
        for (int off = 16; off > 0; off >>= 1)
            v += __shfl_down_sync(0xffffffff, v, off);
        float S0 = __shfl_sync(0xffffffff, v, 0);

        int n = (p & 15) * 8 + warp;
        float An = sA[n];
        float Bqn = g_Bq[bh * NN + n];
        float Ddn = g_Dd[b * NN + n];

        float sv[4], mx = -1e30f;
#pragma unroll
        for (int u = 0; u < 4; ++u) {
            int m = lane + u * 32;
            float x = (m == n) ? (S0 - An + Ddn)
                               : (S0 - An - sA[m] + Bqn + sCk[m]);
            sv[u] = x * SCALE;
            mx = fmaxf(mx, sv[u]);
        }
#pragma unroll
        for (int off = 16; off > 0; off >>= 1)
            mx = fmaxf(mx, __shfl_xor_sync(0xffffffff, mx, off));
        float e[4], tot = 0.f;
#pragma unroll
        for (int u = 0; u < 4; ++u) { e[u] = expf(sv[u] - mx); tot += e[u]; }
#pragma unroll
        for (int off = 16; off > 0; off >>= 1)
            tot += __shfl_xor_sync(0xffffffff, tot, off);
        float inv = 1.f / tot;
        size_t base = ((size_t)(bh * NN) + n) * NN;
#pragma unroll
        for (int u = 0; u < 4; ++u)
            attn_out[base + lane + u * 32] = e[u] * inv;
    }

    // stage2 completion + counter reset for next replay
    __syncthreads();
    if (t == 0) {
        __threadfence();
        unsigned done = atomicAdd(&g_cS2, 1u);
        if (done == 255u) {
            g_cVB = 0u; g_cQK = 0u; g_cDots = 0u; g_cS2 = 0u;
            __threadfence();
        }
    }
}

// ---------------------------------------------------------------------------
// Assembly: sync-free, zero smem, pipelined shfl broadcast, streaming stores.
// Block per (b, jp, iq): 1024 x 256. out[b,i,jp,:] = base + a0*d0 + a1*d1
// ---------------------------------------------------------------------------
__global__ __launch_bounds__(256, 6) void assemble_kernel(
    const float* __restrict__ bo, const float* __restrict__ attn,
    float* __restrict__ out)
{
    int bid = blockIdx.x;
    int iq = bid & 3;
    int bjp = bid >> 2;
    int jp = bjp & 127, b = bjp >> 7;
    int h = jp >> 6, jj = jp & 63;
    int j0 = 2 * jj, j1 = j0 + 1;
    int bh = b * HH + h;

    int t = threadIdx.x;
    int lane = t & 31;
    int sub = t >> 7;
    int c4 = (t & 127) * 4;

    int itn = lane & 15;
    int i_pre = iq * 32 + itn * 2 + sub;
    float aval = attn[((size_t)(bh * NN) + i_pre) * NN + j0 + (lane >> 4)];

    float4 v0 = sum2(&g_Vw[0][0], VW_STRIDE, (size_t)((bh * NN + j0) * 2 + 0) * DM + c4);
    float4 v1 = sum2(&g_Vw[0][0], VW_STRIDE, (size_t)((bh * NN + j1) * 2 + 1) * DM + c4);
    float4 w0 = sum2(&g_Bw[0][0], BW_STRIDE, (size_t)((b  * NN + j0) * 2 + 0) * DM + c4);
    float4 w1 = sum2(&g_Bw[0][0], BW_STRIDE, (size_t)((b  * NN + j1) * 2 + 1) * DM + c4);
    float4 bb = *(const float4*)&bo[c4];

    float4 rb, r0, r1;
    rb.x = v0.x + v1.x + bb.x; rb.y = v0.y + v1.y + bb.y;
    rb.z = v0.z + v1.z + bb.z; rb.w = v0.w + v1.w + bb.w;
    r0.x = w0.x - v0.x; r0.y = w0.y - v0.y; r0.z = w0.z - v0.z; r0.w = w0.w - v0.w;
    r1.x = w1.x - v1.x; r1.y = w1.y - v1.y; r1.z = w1.z - v1.z; r1.w = w1.w - v1.w;

    float a0c = __shfl_sync(0xffffffff, aval, 0);
    float a1c = __shfl_sync(0xffffffff, aval, 16);
#pragma unroll
    for (int it = 0; it < 16; ++it) {
        float a0 = a0c, a1 = a1c;
        if (it < 15) {
            a0c = __shfl_sync(0xffffffff, aval, it + 1);
            a1c = __shfl_sync(0xffffffff, aval, it + 17);
        }
        int i = iq * 32 + it * 2 + sub;
        float4 r;
        r.x = rb.x + a0 * r0.x + a1 * r1.x;
        r.y = rb.y + a0 * r0.y + a1 * r1.y;
        r.z = rb.z + a0 * r0.z + a1 * r1.z;
        r.w = rb.w + a0 * r0.w + a1 * r1.w;
        stcs4(&out[(((size_t)(b * NN + i) * NN) + jp) * DM + c4], r);
    }
}

// ---------------------------------------------------------------------------
extern "C" void kernel_launch(void* const* d_in, const int* in_sizes, int n_in,
                              void* d_out, int out_size)
{
    const float* query = (const float*)d_in[0];
    const float* key   = (const float*)d_in[1];
    const float* value = (const float*)d_in[2];
    const float* boxes = (const float*)d_in[3];
    const float* Wq = (const float*)d_in[4];
    const float* bq = (const float*)d_in[5];
    const float* Wk = (const float*)d_in[6];
    const float* bk = (const float*)d_in[7];
    const float* Wv = (const float*)d_in[8];
    const float* bv = (const float*)d_in[9];
    const float* Wbox = (const float*)d_in[10];
    const float* bbox = (const float*)d_in[11];
    const float* Wo = (const float*)d_in[12];
    const float* bo = (const float*)d_in[13];

    float* out = (float*)d_out;
    float* attn_out = out + OUT_ELEMS;

    stage12_kernel<<<480, 256>>>(query, key, value, boxes,
                                 Wq, bq, Wk, bk, Wv, bv, Wbox, bbox,
                                 Wo, attn_out);
    assemble_kernel<<<BB * NN * 4, 256>>>(bo, attn_out, out);
}